// round 2
// baseline (speedup 1.0000x reference)
#include <cuda_runtime.h>
#include <cstdint>

#define RACE 1024      // K
#define BET  131072    // M (output columns)
#define D1   64
#define D2   16

#define MTILE    128
#define KT       32
#define ASTRIDE  136   // 136 mod 32 == 8 -> conflict-free fragment LDS
#define BSTRIDE  72    // 72  mod 32 == 8
#define H1STRIDE 68    // float4-aligned rows (272 B)

__device__ __forceinline__ unsigned f2tf(float x) {
    unsigned r;
    asm("cvt.rna.tf32.f32 %0, %1;" : "=r"(r) : "f"(x));
    return r;
}

__device__ __forceinline__ void mma_tf32(float c[4],
                                         unsigned a0, unsigned a1, unsigned a2, unsigned a3,
                                         unsigned b0, unsigned b1) {
    asm volatile(
        "mma.sync.aligned.m16n8k8.row.col.f32.tf32.tf32.f32 "
        "{%0,%1,%2,%3},{%4,%5,%6,%7},{%8,%9},{%0,%1,%2,%3};"
        : "+f"(c[0]), "+f"(c[1]), "+f"(c[2]), "+f"(c[3])
        : "r"(a0), "r"(a1), "r"(a2), "r"(a3), "r"(b0), "r"(b1));
}

struct SmemGemm {
    unsigned A[KT * ASTRIDE];   // 4352 words
    unsigned B[KT * BSTRIDE];   // 2304 words
};
struct SmemH1 {
    float h1[MTILE * H1STRIDE]; // 8704 words
};
union SmemU {
    SmemGemm g;
    SmemH1   h;
};

__global__ __launch_bounds__(128)
void mlp_kernel(const float* __restrict__ X,  const float* __restrict__ W1,
                const float* __restrict__ b1, const float* __restrict__ W2,
                const float* __restrict__ b2, const float* __restrict__ W3,
                const float* __restrict__ b3, float* __restrict__ out)
{
    __shared__ SmemU sm;
    __shared__ float W2s[D1 * D2];
    __shared__ float W3s[D2];
    __shared__ float b1s[D1];
    __shared__ float b2s[D2];
    __shared__ float b3s;

    const int tid  = threadIdx.x;
    const int lane = tid & 31;
    const int warp = tid >> 5;
    const int bm   = blockIdx.x * MTILE;

    // Preload small weights into smem
    for (int i = tid; i < D1 * D2; i += 128) W2s[i] = W2[i];
    if (tid < D1) b1s[tid] = b1[tid];
    if (tid < D2) { b2s[tid] = b2[tid]; W3s[tid] = W3[tid]; }
    if (tid == 0) b3s = b3[0];

    // 4 warps: 2 (m) x 2 (n); each warp owns a 64x32 output tile
    const int warp_m = (warp & 1) * 64;
    const int warp_n = (warp >> 1) * 32;
    const int g  = lane >> 2;  // groupID
    const int tg = lane & 3;   // threadID_in_group

    float c[4][4][4];
    #pragma unroll
    for (int mt = 0; mt < 4; mt++)
        #pragma unroll
        for (int nt = 0; nt < 4; nt++)
            #pragma unroll
            for (int i = 0; i < 4; i++) c[mt][nt][i] = 0.f;

    // Staging thread maps (constant over k-chunks)
    const int ks = tid >> 5;          // 0..3   (A: k row base)
    const int m4 = (tid & 31) * 4;    // A: m offset (float4)
    const int kb = tid >> 4;          // 0..7   (B: k row base)
    const int n4 = (tid & 15) * 4;    // B: n offset (float4)

    for (int k0 = 0; k0 < RACE; k0 += KT) {
        __syncthreads();
        // ---- stage A chunk: 32 k-rows x 128 m, fp32 -> tf32 ----
        #pragma unroll
        for (int i = 0; i < 8; i++) {
            int kk = ks + i * 4;
            const float4 v = *reinterpret_cast<const float4*>(
                X + (size_t)(k0 + kk) * BET + bm + m4);
            uint4 t;
            t.x = f2tf(v.x); t.y = f2tf(v.y); t.z = f2tf(v.z); t.w = f2tf(v.w);
            *reinterpret_cast<uint4*>(&sm.g.A[kk * ASTRIDE + m4]) = t;
        }
        // ---- stage B chunk (W1): 32 k-rows x 64 n ----
        #pragma unroll
        for (int i = 0; i < 4; i++) {
            int kk = kb + i * 8;
            const float4 v = *reinterpret_cast<const float4*>(
                W1 + (k0 + kk) * D1 + n4);
            uint4 t;
            t.x = f2tf(v.x); t.y = f2tf(v.y); t.z = f2tf(v.z); t.w = f2tf(v.w);
            *reinterpret_cast<uint4*>(&sm.g.B[kk * BSTRIDE + n4]) = t;
        }
        __syncthreads();

        // ---- mma over the chunk: 4 k-steps of 8 ----
        #pragma unroll
        for (int kk = 0; kk < KT; kk += 8) {
            unsigned a[4][4], b[4][2];
            #pragma unroll
            for (int mt = 0; mt < 4; mt++) {
                int r = warp_m + mt * 16 + g;
                a[mt][0] = sm.g.A[(kk + tg)     * ASTRIDE + r];
                a[mt][1] = sm.g.A[(kk + tg)     * ASTRIDE + r + 8];
                a[mt][2] = sm.g.A[(kk + tg + 4) * ASTRIDE + r];
                a[mt][3] = sm.g.A[(kk + tg + 4) * ASTRIDE + r + 8];
            }
            #pragma unroll
            for (int nt = 0; nt < 4; nt++) {
                int n = warp_n + nt * 8 + g;
                b[nt][0] = sm.g.B[(kk + tg)     * BSTRIDE + n];
                b[nt][1] = sm.g.B[(kk + tg + 4) * BSTRIDE + n];
            }
            #pragma unroll
            for (int mt = 0; mt < 4; mt++)
                #pragma unroll
                for (int nt = 0; nt < 4; nt++)
                    mma_tf32(c[mt][nt], a[mt][0], a[mt][1], a[mt][2], a[mt][3],
                             b[nt][0], b[nt][1]);
        }
    }

    // ---- epilogue layer 1: bias + relu -> h1 tile in smem (overlays A/B) ----
    __syncthreads();
    #pragma unroll
    for (int mt = 0; mt < 4; mt++) {
        #pragma unroll
        for (int nt = 0; nt < 4; nt++) {
            int col = warp_n + nt * 8 + 2 * tg;
            int r0  = warp_m + mt * 16 + g;
            sm.h.h1[r0 * H1STRIDE + col]           = fmaxf(c[mt][nt][0] + b1s[col],     0.f);
            sm.h.h1[r0 * H1STRIDE + col + 1]       = fmaxf(c[mt][nt][1] + b1s[col + 1], 0.f);
            sm.h.h1[(r0 + 8) * H1STRIDE + col]     = fmaxf(c[mt][nt][2] + b1s[col],     0.f);
            sm.h.h1[(r0 + 8) * H1STRIDE + col + 1] = fmaxf(c[mt][nt][3] + b1s[col + 1], 0.f);
        }
    }
    __syncthreads();

    // ---- layers 2 + 3: one thread per output column, exact fp32 ----
    {
        const int r = tid;  // 0..127
        float x[D1];
        #pragma unroll
        for (int i = 0; i < 16; i++) {
            float4 v = *reinterpret_cast<const float4*>(&sm.h.h1[r * H1STRIDE + i * 4]);
            x[i * 4] = v.x; x[i * 4 + 1] = v.y; x[i * 4 + 2] = v.z; x[i * 4 + 3] = v.w;
        }
        float acc[D2];
        #pragma unroll
        for (int d = 0; d < D2; d++) acc[d] = b2s[d];
        #pragma unroll
        for (int d1 = 0; d1 < D1; d1++) {
            float xv = x[d1];
            #pragma unroll
            for (int d2 = 0; d2 < D2; d2++)
                acc[d2] = fmaf(xv, W2s[d1 * D2 + d2], acc[d2]);
        }
        float o = b3s;
        #pragma unroll
        for (int d = 0; d < D2; d++) o += fmaxf(acc[d], 0.f) * W3s[d];
        out[bm + r] = o;
    }
}

extern "C" void kernel_launch(void* const* d_in, const int* in_sizes, int n_in,
                              void* d_out, int out_size)
{
    const float* X  = (const float*)d_in[0];
    const float* W1 = (const float*)d_in[1];
    const float* b1 = (const float*)d_in[2];
    const float* W2 = (const float*)d_in[3];
    const float* b2 = (const float*)d_in[4];
    const float* W3 = (const float*)d_in[5];
    const float* b3 = (const float*)d_in[6];
    (void)in_sizes; (void)n_in; (void)out_size;

    mlp_kernel<<<BET / MTILE, 128>>>(X, W1, b1, W2, b2, W3, b3, (float*)d_out);
}